// round 15
// baseline (speedup 1.0000x reference)
#include <cuda_runtime.h>
#include <cuda_bf16.h>
#include <math.h>
#include <stdint.h>

#define BATCH 16
#define HW    4096
#define CHW   1048576u
#define PS    16777216ull   // plane stride (elements) in g_ybf

// Scratch (no allocation allowed -> __device__ globals)
__device__ __nv_bfloat16 g_ybf[6ull * 16777216ull];  // Fh,Fl,Gh,Gl,Hh,Hl planes (192MB)
__device__ float g_o[16777216ull];          // attention output (tf32-rounded)
__device__ float g_xrF[16777216ull];        // x, tf32-rounded, B-fragment layout
__device__ float g_wtF[768 * 256];          // concat(wf,wg,wh), A-fragment layout
__device__ float g_wtvF[256 * 256];         // wv, A-fragment layout
__device__ float g_bcat[768];

__device__ __forceinline__ uint32_t f2tf32(float v) {
    uint32_t r;
    asm("cvt.rna.tf32.f32 %0, %1;" : "=r"(r) : "f"(v));
    return r;
}
__device__ __forceinline__ float rtf(float v) { return __uint_as_float(f2tf32(v)); }

__device__ __forceinline__ void mma_tf32(float* c, const uint32_t* a, const uint32_t* b) {
    asm volatile(
        "mma.sync.aligned.m16n8k8.row.col.f32.tf32.tf32.f32 "
        "{%0,%1,%2,%3}, {%4,%5,%6,%7}, {%8,%9}, {%0,%1,%2,%3};"
        : "+f"(c[0]), "+f"(c[1]), "+f"(c[2]), "+f"(c[3])
        : "r"(a[0]), "r"(a[1]), "r"(a[2]), "r"(a[3]), "r"(b[0]), "r"(b[1]));
}

__device__ __forceinline__ void mma_bf16(float* c, const uint32_t* a, const uint32_t* b) {
    asm volatile(
        "mma.sync.aligned.m16n8k16.row.col.f32.bf16.bf16.f32 "
        "{%0,%1,%2,%3}, {%4,%5,%6,%7}, {%8,%9}, {%0,%1,%2,%3};"
        : "+f"(c[0]), "+f"(c[1]), "+f"(c[2]), "+f"(c[3])
        : "r"(a[0]), "r"(a[1]), "r"(a[2]), "r"(a[3]), "r"(b[0]), "r"(b[1]));
}

// pack two f32 into bf16x2: low half = first arg, high = second
__device__ __forceinline__ uint32_t bfpack(float lo_elem, float hi_elem) {
    uint32_t r;
    asm("cvt.rn.bf16x2.f32 %0, %2, %1;" : "=r"(r) : "f"(lo_elem), "f"(hi_elem));
    return r;
}
__device__ __forceinline__ void bfsplit2(float x0, float x1, uint32_t& hi, uint32_t& lo) {
    hi = bfpack(x0, x1);
    float h0 = __uint_as_float(hi << 16);
    float h1 = __uint_as_float(hi & 0xffff0000u);
    lo = bfpack(x0 - h0, x1 - h1);
}

__device__ __forceinline__ void cpa16(uint32_t s, const void* g) {
    asm volatile("cp.async.cg.shared.global [%0], [%1], 16;" :: "r"(s), "l"(g));
}
#define CP_COMMIT()  asm volatile("cp.async.commit_group;" ::: "memory")
#define CP_WAIT3()   asm volatile("cp.async.wait_group 3;" ::: "memory")
#define CP_WAIT0()   asm volatile("cp.async.wait_group 0;" ::: "memory")

#define LDSM4T(r0,r1,r2,r3,a) \
    asm volatile("ldmatrix.sync.aligned.m8n8.x4.trans.shared.b16 {%0,%1,%2,%3}, [%4];" \
                 : "=r"(r0),"=r"(r1),"=r"(r2),"=r"(r3) : "r"(a))
#define LDSM2T(r0,r1,a) \
    asm volatile("ldmatrix.sync.aligned.m8n8.x2.trans.shared.b16 {%0,%1}, [%2];" \
                 : "=r"(r0),"=r"(r1) : "r"(a))
#define LDSM4N(r0,r1,r2,r3,a) \
    asm volatile("ldmatrix.sync.aligned.m8n8.x4.shared.b16 {%0,%1,%2,%3}, [%4];" \
                 : "=r"(r0),"=r"(r1),"=r"(r2),"=r"(r3) : "r"(a))
#define LDSM2N(r0,r1,a) \
    asm volatile("ldmatrix.sync.aligned.m8n8.x2.shared.b16 {%0,%1}, [%2];" \
                 : "=r"(r0),"=r"(r1) : "r"(a))

// ---------------------------------------------------------------------------
// Prep: weights -> A-fragment layout, tf32-rounded; concat biases.
// ---------------------------------------------------------------------------
__global__ void prep_w_kernel(const float* __restrict__ wf, const float* __restrict__ wg,
                              const float* __restrict__ wh, const float* __restrict__ wv,
                              const float* __restrict__ bf, const float* __restrict__ bg,
                              const float* __restrict__ bh) {
    int idx = blockIdx.x * 256 + threadIdx.x;
    int lane = idx & 31;
    int t1 = idx >> 5;
    int mf = t1 & 7;  t1 >>= 3;
    int kk = t1 & 1;  t1 >>= 1;
    int ks = t1 & 15; t1 >>= 4;
    int qr = lane >> 2, qc = lane & 3;
    int k = ks * 16 + kk * 8 + qc;
    float4 v;
    if (idx < 49152) {
        int m = t1 * 128 + (mf >> 2) * 64 + (mf & 3) * 16 + qr;
        const float* w = (m < 256) ? wf : (m < 512) ? wg : wh;
        int mm = m & 255;
        v.x = rtf(w[mm * 256 + k]);
        v.y = rtf(w[(mm + 8) * 256 + k]);
        v.z = rtf(w[mm * 256 + k + 4]);
        v.w = rtf(w[(mm + 8) * 256 + k + 4]);
        *(float4*)&g_wtF[idx * 4] = v;
    } else {
        int idx2 = idx - 49152;
        int t2 = idx2 >> 5;
        int mf2 = t2 & 7;  t2 >>= 3;
        int kk2 = t2 & 1;  t2 >>= 1;
        int ks2 = t2 & 15; t2 >>= 4;
        int lane2 = idx2 & 31;
        int qr2 = lane2 >> 2, qc2 = lane2 & 3;
        int k2 = ks2 * 16 + kk2 * 8 + qc2;
        int m = t2 * 128 + (mf2 >> 2) * 64 + (mf2 & 3) * 16 + qr2;
        v.x = rtf(wv[m * 256 + k2]);
        v.y = rtf(wv[(m + 8) * 256 + k2]);
        v.z = rtf(wv[m * 256 + k2 + 4]);
        v.w = rtf(wv[(m + 8) * 256 + k2 + 4]);
        *(float4*)&g_wtvF[idx2 * 4] = v;
    }
    if (idx < 256) {
        g_bcat[idx]       = bf[idx];
        g_bcat[256 + idx] = bg[idx];
        g_bcat[512 + idx] = bh[idx];
    }
}

// x -> B-fragment layout, tf32-rounded
__global__ void x_frag_kernel(const float* __restrict__ x) {
    int idx = blockIdx.x * 256 + threadIdx.x;
    int lane = idx & 31;
    int t1 = idx >> 5;
    int nf = t1 & 15; t1 >>= 4;
    int kk = t1 & 1;  t1 >>= 1;
    int ks = t1 & 15; t1 >>= 4;
    int nt = t1 & 31; t1 >>= 5;
    int n = nt * 128 + (nf >> 2) * 32 + (nf & 3) * 8 + (lane >> 2);
    int k = ks * 16 + kk * 8 + (lane & 3);
    const float* xb = x + (size_t)t1 * CHW;
    float2 v;
    v.x = rtf(xb[(size_t)k * HW + n]);
    v.y = rtf(xb[(size_t)(k + 4) * HW + n]);
    *(float2*)&g_xrF[(size_t)idx * 2] = v;
}

// ---------------------------------------------------------------------------
// HMMA tf32 conv GEMM (round-12 pipeline). BFRAG=true (conv1) writes bf16
// hi/lo planes into g_ybf (bit-identical to attn's former bfsplit of the f32
// values); BFRAG=false (conv2) writes f32 to d_out.
// ---------------------------------------------------------------------------
#define SSTRIDE 136
#define SA(s)       ((s) * 2048)
#define SBF(s)      (10240 + (s) * 2048)
#define SBR(s, kr)  (10240 + (s) * 2176 + (kr) * SSTRIDE)
#define CONV_SMEM   ((10240 + 5 * 2176) * 4)   // 84480 B

template <bool BFRAG>
__global__ __launch_bounds__(256, 2)
void conv_mma_kernel(const float* __restrict__ XB, const float* __restrict__ WTF,
                     const float* __restrict__ bias, float* __restrict__ Y) {
    extern __shared__ uint32_t dsm[];

    const int tid  = threadIdx.x;
    const int lane = tid & 31;
    const int warp = tid >> 5;
    const int mw   = warp >> 2;
    const int nw   = warp & 3;
    const int b    = blockIdx.z;
    const int nt   = blockIdx.x;
    const int n0   = nt * 128;
    const int mt   = blockIdx.y;
    const int m0   = mt * 128;

    const uint32_t sbase = (uint32_t)__cvta_generic_to_shared(dsm);
    const float* gA = WTF + (size_t)(mt * 16) * 2048;
    const float* gBF = XB + ((size_t)(b * 32 + nt) * 16) * 2048;
    const float* gBR = XB + (size_t)b * CHW + n0;

    float acc[4][4][4];
#pragma unroll
    for (int i = 0; i < 4; i++)
#pragma unroll
        for (int j = 0; j < 4; j++)
#pragma unroll
            for (int r = 0; r < 4; r++) acc[i][j][r] = 0.f;

    auto load_stage = [&](int s, int buf) {
#pragma unroll
        for (int h = 0; h < 2; h++) {
            int c = tid + h * 256;
            cpa16(sbase + (SA(buf) + c * 4) * 4, gA + (size_t)s * 2048 + c * 4);
            if (BFRAG) {
                cpa16(sbase + (SBF(buf) + c * 4) * 4, gBF + (size_t)s * 2048 + c * 4);
            } else {
                int kr = c >> 5, nc = (c & 31) * 4;
                cpa16(sbase + (SBR(buf, kr) + nc) * 4,
                      gBR + (size_t)(s * 16 + kr) * HW + nc);
            }
        }
    };

#pragma unroll
    for (int s = 0; s < 3; s++) { load_stage(s, s); CP_COMMIT(); }

    int buf = 0, nbuf = 3;
    for (int kt = 0; kt < 16; kt++) {
        if (kt < 13) load_stage(kt + 3, nbuf);
        CP_COMMIT();
        CP_WAIT3();
        __syncthreads();

#pragma unroll
        for (int kk = 0; kk < 2; kk++) {
            uint32_t af[4][4];
#pragma unroll
            for (int mi = 0; mi < 4; mi++) {
                const uint4 a4 = *(const uint4*)
                    &dsm[SA(buf) + ((kk * 8 + mw * 4 + mi) * 32 + lane) * 4];
                af[mi][0] = a4.x; af[mi][1] = a4.y; af[mi][2] = a4.z; af[mi][3] = a4.w;
            }
            uint32_t bfr[4][2];
            if (BFRAG) {
#pragma unroll
                for (int nj = 0; nj < 4; nj++) {
                    const uint2 b2 = *(const uint2*)
                        &dsm[SBF(buf) + ((kk * 16 + nw * 4 + nj) * 32 + lane) * 2];
                    bfr[nj][0] = b2.x; bfr[nj][1] = b2.y;
                }
            } else {
                const int qc = lane & 3, qr = lane >> 2;
                const uint32_t* B0 = dsm + SBR(buf, kk * 8 + qc) + nw * 32 + qr;
#pragma unroll
                for (int nj = 0; nj < 4; nj++) {
                    bfr[nj][0] = B0[nj * 8];
                    bfr[nj][1] = B0[4 * SSTRIDE + nj * 8];
                }
            }
#pragma unroll
            for (int mi = 0; mi < 4; mi++)
#pragma unroll
                for (int nj = 0; nj < 4; nj++)
                    mma_tf32(acc[mi][nj], af[mi], bfr[nj]);
        }
        if (++buf == 5)  buf = 0;
        if (++nbuf == 5) nbuf = 0;
    }

    if (BFRAG) {
        // conv1 epilogue: bias + bf16 hi/lo split, written to g_ybf planes.
        // plane index = 2*(mr>>8) (hi), +1 (lo); element = b*CHW + (mr&255)*HW + n.
        uint32_t* Yb = (uint32_t*)Y;                 // g_ybf viewed as u32 (bf16 pairs)
        const size_t LOD = PS >> 1;                  // +1 plane, in u32 units
#pragma unroll
        for (int mi = 0; mi < 4; mi++) {
            int mr0 = m0 + mw * 64 + mi * 16 + (lane >> 2);
            float bv0 = bias[mr0];
            float bv1 = bias[mr0 + 8];
            int pl = (mr0 >> 8) * 2, c0 = mr0 & 255;
            size_t e0 = (((size_t)pl * 16 + b) * CHW + (size_t)c0 * HW + n0) >> 1;
            size_t e1 = e0 + (size_t)(8 * HW >> 1);  // row mr0+8
#pragma unroll
            for (int nj = 0; nj < 4; nj++) {
                int nc2 = (nw * 32 + nj * 8 + 2 * (lane & 3)) >> 1;
                uint32_t h, l;
                bfsplit2(acc[mi][nj][0] + bv0, acc[mi][nj][1] + bv0, h, l);
                Yb[e0 + nc2] = h;  Yb[e0 + LOD + nc2] = l;
                bfsplit2(acc[mi][nj][2] + bv1, acc[mi][nj][3] + bv1, h, l);
                Yb[e1 + nc2] = h;  Yb[e1 + LOD + nc2] = l;
            }
        }
    } else {
        // conv2 epilogue: bias + f32 v2 stores to d_out
#pragma unroll
        for (int mi = 0; mi < 4; mi++) {
            int mr0 = m0 + mw * 64 + mi * 16 + (lane >> 2);
            float bv0 = bias[mr0];
            float bv1 = bias[mr0 + 8];
            float* y0 = Y + (size_t)b * CHW + (size_t)(mr0 & 255) * HW + n0;
            float* y1 = Y + (size_t)b * CHW + (size_t)((mr0 + 8) & 255) * HW + n0;
#pragma unroll
            for (int nj = 0; nj < 4; nj++) {
                int nc = nw * 32 + nj * 8 + 2 * (lane & 3);
                float2 v0 = make_float2(acc[mi][nj][0] + bv0, acc[mi][nj][1] + bv0);
                float2 v1 = make_float2(acc[mi][nj][2] + bv1, acc[mi][nj][3] + bv1);
                *(float2*)(y0 + nc) = v0;
                *(float2*)(y1 + nc) = v1;
            }
        }
    }
}

// ---------------------------------------------------------------------------
// Fused attention: F/G/Hm arrive as pre-split bf16 hi/lo planes -> pure
// cp.async copies into the ldmatrix-ready smem layout (no cvt in load paths).
// GEMM1 tf32-equivalent bf16x2 x3, split softmax, GEMM2 bf16x2 x3. Unchanged
// math; only the data movement changed.
// ---------------------------------------------------------------------------
#define WS   36
#define PL   2304
#define ATT_SMEM 37888

__global__ __launch_bounds__(256)
void attn_kernel(const __nv_bfloat16* __restrict__ yb, float* __restrict__ o) {
    extern __shared__ uint32_t sm[];
    const int bc = blockIdx.x;
    const __nv_bfloat16* Fh = yb + (size_t)bc * HW;
    const __nv_bfloat16* Fl = Fh + PS;
    const __nv_bfloat16* Gh = Fh + 2 * PS;
    const __nv_bfloat16* Gl = Fh + 3 * PS;
    const __nv_bfloat16* Hh = Fh + 4 * PS;
    const __nv_bfloat16* Hl = Fh + 5 * PS;

    float* red = (float*)(sm + 4 * PL);   // [64][4]

    const uint32_t sb = (uint32_t)__cvta_generic_to_shared(sm);
    const int tid  = threadIdx.x;
    const int lane = tid & 31;
    const int warp = tid >> 5;
    const int mt   = warp >> 1;
    const int nh   = warp & 1;
    const int qr   = lane >> 2;
    const int qc   = lane & 3;

    // phase 0: copy F,G hi/lo planes into [h][w-pair] smem (stride WS) via cp.async
#pragma unroll
    for (int it = 0; it < 2; it++) {
        int i = tid * 8 + it * 2048;                    // element within plane
        int off = (i >> 6) * WS + ((i & 63) >> 1);      // u32 offset in plane
        cpa16(sb + (0 * PL + off) * 4, Fh + i);
        cpa16(sb + (1 * PL + off) * 4, Fl + i);
        cpa16(sb + (2 * PL + off) * 4, Gh + i);
        cpa16(sb + (3 * PL + off) * 4, Gl + i);
    }
    CP_COMMIT();
    CP_WAIT0();
    __syncthreads();

    // GEMM1 (bf16x2): S[w][v] = sum_h F[h][w] G[h][v]; operands via ldmatrix.trans
    float acc[4][4];
#pragma unroll
    for (int nj = 0; nj < 4; nj++)
#pragma unroll
        for (int r = 0; r < 4; r++) acc[nj][r] = 0.f;

    const int kselA = (lane & 7) + 8 * ((lane >> 4) & 1);
    const int mcolA = mt * 16 + 8 * ((lane >> 3) & 1);
    const int kselB = (lane & 7) + 8 * ((lane >> 3) & 1);
#pragma unroll
    for (int it = 0; it < 4; it++) {
        uint32_t aaddr = sb + ((it * 16 + kselA) * WS) * 4 + mcolA * 2;
        uint32_t aH[4], aL[4];
        LDSM4T(aH[0], aH[1], aH[2], aH[3], aaddr);
        LDSM4T(aL[0], aL[1], aL[2], aL[3], aaddr + PL * 4);
        uint32_t bbase = sb + 2 * PL * 4 + ((it * 16 + kselB) * WS) * 4 + (nh * 32) * 2;
#pragma unroll
        for (int nj = 0; nj < 4; nj++) {
            uint32_t bH[2], bL[2];
            LDSM2T(bH[0], bH[1], bbase + nj * 16);
            LDSM2T(bL[0], bL[1], bbase + nj * 16 + PL * 4);
            mma_bf16(acc[nj], aH, bH);
            mma_bf16(acc[nj], aH, bL);
            mma_bf16(acc[nj], aL, bH);
        }
    }

    // split softmax
    float mlo = -1e30f, mhi = -1e30f;
#pragma unroll
    for (int nj = 0; nj < 4; nj++) {
        mlo = fmaxf(mlo, fmaxf(acc[nj][0], acc[nj][1]));
        mhi = fmaxf(mhi, fmaxf(acc[nj][2], acc[nj][3]));
    }
    mlo = fmaxf(mlo, __shfl_xor_sync(0xffffffffu, mlo, 1));
    mlo = fmaxf(mlo, __shfl_xor_sync(0xffffffffu, mlo, 2));
    mhi = fmaxf(mhi, __shfl_xor_sync(0xffffffffu, mhi, 1));
    mhi = fmaxf(mhi, __shfl_xor_sync(0xffffffffu, mhi, 2));
    float slo = 0.f, shi = 0.f;
#pragma unroll
    for (int nj = 0; nj < 4; nj++) {
        acc[nj][0] = __expf(acc[nj][0] - mlo);
        acc[nj][1] = __expf(acc[nj][1] - mlo);
        acc[nj][2] = __expf(acc[nj][2] - mhi);
        acc[nj][3] = __expf(acc[nj][3] - mhi);
        slo += acc[nj][0] + acc[nj][1];
        shi += acc[nj][2] + acc[nj][3];
    }
    slo += __shfl_xor_sync(0xffffffffu, slo, 1);
    slo += __shfl_xor_sync(0xffffffffu, slo, 2);
    shi += __shfl_xor_sync(0xffffffffu, shi, 1);
    shi += __shfl_xor_sync(0xffffffffu, shi, 2);

    const int rlo = mt * 16 + qr, rhi = rlo + 8;
    if (qc == 0) {
        red[rlo * 4 + nh * 2]     = mlo;
        red[rlo * 4 + nh * 2 + 1] = slo;
        red[rhi * 4 + nh * 2]     = mhi;
        red[rhi * 4 + nh * 2 + 1] = shi;
    }
    __syncthreads();   // all GEMM1 plane reads complete; red published

    // phase 2 Hm copy issued NOW (overlaps combine + attn staging); overlays
    // the F planes (safe: all GEMM1 reads are behind the barrier above)
#pragma unroll
    for (int it = 0; it < 2; it++) {
        int i = tid * 8 + it * 2048;
        int off = (i >> 6) * WS + ((i & 63) >> 1);
        cpa16(sb + (0 * PL + off) * 4, Hh + i);
        cpa16(sb + (1 * PL + off) * 4, Hl + i);
    }
    CP_COMMIT();

    float scl_lo, scl_hi;
    {
        float4 r4 = *(const float4*)&red[rlo * 4];
        float M = fmaxf(r4.x, r4.z);
        float den = r4.y * __expf(r4.x - M) + r4.w * __expf(r4.z - M);
        scl_lo = __expf(mlo - M) / den;
        r4 = *(const float4*)&red[rhi * 4];
        M = fmaxf(r4.x, r4.z);
        den = r4.y * __expf(r4.x - M) + r4.w * __expf(r4.z - M);
        scl_hi = __expf(mhi - M) / den;
    }

    // attn -> [v][w] scalar bf16 hi/lo (overlays G planes, also behind barrier)
    {
        uint32_t* sAtH = sm + 2 * PL;
        uint32_t* sAtL = sm + 3 * PL;
        __nv_bfloat16* pH = (__nv_bfloat16*)sAtH;
        __nv_bfloat16* pL = (__nv_bfloat16*)sAtL;
        const int wlo = mt * 16 + qr, whi = wlo + 8;
#pragma unroll
        for (int nj = 0; nj < 4; nj++) {
            const int v = nh * 32 + nj * 8 + 2 * qc;
#pragma unroll
            for (int r = 0; r < 4; r++) {
                float val = acc[nj][r] * ((r < 2) ? scl_lo : scl_hi);
                int vv = v + (r & 1);
                int ww = (r < 2) ? wlo : whi;
                __nv_bfloat16 h = __float2bfloat16_rn(val);
                pH[vv * (WS * 2) + ww] = h;
                pL[vv * (WS * 2) + ww] = __float2bfloat16_rn(val - __bfloat162float(h));
            }
        }
    }
    CP_WAIT0();
    __syncthreads();

    // GEMM2 (bf16x2): C[v][h] = sum_w attn[w][v] * Hm[h][w]  (= O^T), ldmatrix non-trans
#pragma unroll
    for (int nj = 0; nj < 4; nj++)
#pragma unroll
        for (int r = 0; r < 4; r++) acc[nj][r] = 0.f;

    const int mrowA2 = mt * 16 + (lane & 7) + 8 * ((lane >> 3) & 1);
    const int kcolA2 = 8 * ((lane >> 4) & 1);
    const int nrowB2 = nh * 32 + (lane & 7);
    const int kcolB2 = 8 * ((lane >> 3) & 1);
#pragma unroll
    for (int it = 0; it < 4; it++) {
        uint32_t aaddr = sb + 2 * PL * 4 + (mrowA2 * WS) * 4 + (it * 16 + kcolA2) * 2;
        uint32_t aH[4], aL[4];
        LDSM4N(aH[0], aH[1], aH[2], aH[3], aaddr);
        LDSM4N(aL[0], aL[1], aL[2], aL[3], aaddr + PL * 4);
#pragma unroll
        for (int nj = 0; nj < 4; nj++) {
            uint32_t baddr = sb + ((nrowB2 + nj * 8) * WS) * 4 + (it * 16 + kcolB2) * 2;
            uint32_t bH[2], bL[2];
            LDSM2N(bH[0], bH[1], baddr);
            LDSM2N(bL[0], bL[1], baddr + PL * 4);
            mma_bf16(acc[nj], aH, bH);
            mma_bf16(acc[nj], aH, bL);
            mma_bf16(acc[nj], aL, bH);
        }
    }

    // store O[h][v] (tf32-rounded for the final conv)
    float* O = o + (size_t)bc * HW;
    const int vr = mt * 16 + qr;
#pragma unroll
    for (int nj = 0; nj < 4; nj++) {
        const int hc = nh * 32 + nj * 8 + 2 * qc;
        O[hc * 64 + vr]           = rtf(acc[nj][0]);
        O[(hc + 1) * 64 + vr]     = rtf(acc[nj][1]);
        O[hc * 64 + vr + 8]       = rtf(acc[nj][2]);
        O[(hc + 1) * 64 + vr + 8] = rtf(acc[nj][3]);
    }
}

// ---------------------------------------------------------------------------
extern "C" void kernel_launch(void* const* d_in, const int* in_sizes, int n_in,
                              void* d_out, int out_size) {
    const float* x  = (const float*)d_in[0];
    const float* wf = (const float*)d_in[1];
    const float* bf = (const float*)d_in[2];
    const float* wg = (const float*)d_in[3];
    const float* bg = (const float*)d_in[4];
    const float* wh = (const float*)d_in[5];
    const float* bh = (const float*)d_in[6];
    const float* wv = (const float*)d_in[7];
    const float* bv = (const float*)d_in[8];

    float *ob, *xrF, *wtF, *wtvF, *bcat;
    __nv_bfloat16* ybf;
    cudaGetSymbolAddress((void**)&ybf,  g_ybf);
    cudaGetSymbolAddress((void**)&ob,   g_o);
    cudaGetSymbolAddress((void**)&xrF,  g_xrF);
    cudaGetSymbolAddress((void**)&wtF,  g_wtF);
    cudaGetSymbolAddress((void**)&wtvF, g_wtvF);
    cudaGetSymbolAddress((void**)&bcat, g_bcat);

    cudaFuncSetAttribute(conv_mma_kernel<true>,
                         cudaFuncAttributeMaxDynamicSharedMemorySize, CONV_SMEM);
    cudaFuncSetAttribute(conv_mma_kernel<false>,
                         cudaFuncAttributeMaxDynamicSharedMemorySize, CONV_SMEM);
    cudaFuncSetAttribute(attn_kernel,
                         cudaFuncAttributeMaxDynamicSharedMemorySize, ATT_SMEM);

    // 1) weights -> fragment layout; x -> fragment layout (tf32-rounded)
    prep_w_kernel<<<256, 256>>>(wf, wg, wh, wv, bf, bg, bh);
    x_frag_kernel<<<32768, 256>>>(x);

    // 2) fused f/g/h conv -> bf16 hi/lo planes
    conv_mma_kernel<true><<<dim3(32, 6, 16), 256, CONV_SMEM>>>(xrF, wtF, bcat, (float*)ybf);

    // 3) per-(b,c) attention
    attn_kernel<<<4096, 256, ATT_SMEM>>>(ybf, ob);

    // 4) output conv
    conv_mma_kernel<false><<<dim3(32, 2, 16), 256, CONV_SMEM>>>(ob, wtvF, bv, (float*)d_out);
}

// round 16
// speedup vs baseline: 1.0386x; 1.0386x over previous
#include <cuda_runtime.h>
#include <cuda_bf16.h>
#include <math.h>
#include <stdint.h>

#define BATCH 16
#define HW    4096
#define CHW   1048576u
#define PS    16777216ull   // plane stride (elements) in g_ybf

// Scratch (no allocation allowed -> __device__ globals)
__device__ __nv_bfloat16 g_ybf[6ull * 16777216ull];  // Fh,Fl,Gh,Gl,Hh,Hl planes (192MB)
__device__ float g_o[16777216ull];          // attention output (tf32-rounded)
__device__ float g_xrF[16777216ull];        // x, tf32-rounded, B-fragment layout
__device__ float g_wtF[768 * 256];          // concat(wf,wg,wh), A-fragment layout
__device__ float g_wtvF[256 * 256];         // wv, A-fragment layout
__device__ float g_bcat[768];

__device__ __forceinline__ uint32_t f2tf32(float v) {
    uint32_t r;
    asm("cvt.rna.tf32.f32 %0, %1;" : "=r"(r) : "f"(v));
    return r;
}
__device__ __forceinline__ float rtf(float v) { return __uint_as_float(f2tf32(v)); }

__device__ __forceinline__ void mma_tf32(float* c, const uint32_t* a, const uint32_t* b) {
    asm volatile(
        "mma.sync.aligned.m16n8k8.row.col.f32.tf32.tf32.f32 "
        "{%0,%1,%2,%3}, {%4,%5,%6,%7}, {%8,%9}, {%0,%1,%2,%3};"
        : "+f"(c[0]), "+f"(c[1]), "+f"(c[2]), "+f"(c[3])
        : "r"(a[0]), "r"(a[1]), "r"(a[2]), "r"(a[3]), "r"(b[0]), "r"(b[1]));
}

__device__ __forceinline__ void mma_bf16(float* c, const uint32_t* a, const uint32_t* b) {
    asm volatile(
        "mma.sync.aligned.m16n8k16.row.col.f32.bf16.bf16.f32 "
        "{%0,%1,%2,%3}, {%4,%5,%6,%7}, {%8,%9}, {%0,%1,%2,%3};"
        : "+f"(c[0]), "+f"(c[1]), "+f"(c[2]), "+f"(c[3])
        : "r"(a[0]), "r"(a[1]), "r"(a[2]), "r"(a[3]), "r"(b[0]), "r"(b[1]));
}

// pack two f32 into bf16x2: low half = first arg, high = second
__device__ __forceinline__ uint32_t bfpack(float lo_elem, float hi_elem) {
    uint32_t r;
    asm("cvt.rn.bf16x2.f32 %0, %2, %1;" : "=r"(r) : "f"(lo_elem), "f"(hi_elem));
    return r;
}
__device__ __forceinline__ void bfsplit2(float x0, float x1, uint32_t& hi, uint32_t& lo) {
    hi = bfpack(x0, x1);
    float h0 = __uint_as_float(hi << 16);
    float h1 = __uint_as_float(hi & 0xffff0000u);
    lo = bfpack(x0 - h0, x1 - h1);
}

__device__ __forceinline__ void cpa16(uint32_t s, const void* g) {
    asm volatile("cp.async.cg.shared.global [%0], [%1], 16;" :: "r"(s), "l"(g));
}
#define CP_COMMIT()  asm volatile("cp.async.commit_group;" ::: "memory")
#define CP_WAIT3()   asm volatile("cp.async.wait_group 3;" ::: "memory")
#define CP_WAIT0()   asm volatile("cp.async.wait_group 0;" ::: "memory")

#define LDSM4T(r0,r1,r2,r3,a) \
    asm volatile("ldmatrix.sync.aligned.m8n8.x4.trans.shared.b16 {%0,%1,%2,%3}, [%4];" \
                 : "=r"(r0),"=r"(r1),"=r"(r2),"=r"(r3) : "r"(a))
#define LDSM2T(r0,r1,a) \
    asm volatile("ldmatrix.sync.aligned.m8n8.x2.trans.shared.b16 {%0,%1}, [%2];" \
                 : "=r"(r0),"=r"(r1) : "r"(a))
#define LDSM4N(r0,r1,r2,r3,a) \
    asm volatile("ldmatrix.sync.aligned.m8n8.x4.shared.b16 {%0,%1,%2,%3}, [%4];" \
                 : "=r"(r0),"=r"(r1),"=r"(r2),"=r"(r3) : "r"(a))
#define LDSM2N(r0,r1,a) \
    asm volatile("ldmatrix.sync.aligned.m8n8.x2.shared.b16 {%0,%1}, [%2];" \
                 : "=r"(r0),"=r"(r1) : "r"(a))

// ---------------------------------------------------------------------------
// Prep: weights -> A-fragment layout, tf32-rounded; concat biases.
// ---------------------------------------------------------------------------
__global__ void prep_w_kernel(const float* __restrict__ wf, const float* __restrict__ wg,
                              const float* __restrict__ wh, const float* __restrict__ wv,
                              const float* __restrict__ bf, const float* __restrict__ bg,
                              const float* __restrict__ bh) {
    int idx = blockIdx.x * 256 + threadIdx.x;
    int lane = idx & 31;
    int t1 = idx >> 5;
    int mf = t1 & 7;  t1 >>= 3;
    int kk = t1 & 1;  t1 >>= 1;
    int ks = t1 & 15; t1 >>= 4;
    int qr = lane >> 2, qc = lane & 3;
    int k = ks * 16 + kk * 8 + qc;
    float4 v;
    if (idx < 49152) {
        int m = t1 * 128 + (mf >> 2) * 64 + (mf & 3) * 16 + qr;
        const float* w = (m < 256) ? wf : (m < 512) ? wg : wh;
        int mm = m & 255;
        v.x = rtf(w[mm * 256 + k]);
        v.y = rtf(w[(mm + 8) * 256 + k]);
        v.z = rtf(w[mm * 256 + k + 4]);
        v.w = rtf(w[(mm + 8) * 256 + k + 4]);
        *(float4*)&g_wtF[idx * 4] = v;
    } else {
        int idx2 = idx - 49152;
        int t2 = idx2 >> 5;
        int mf2 = t2 & 7;  t2 >>= 3;
        int kk2 = t2 & 1;  t2 >>= 1;
        int ks2 = t2 & 15; t2 >>= 4;
        int lane2 = idx2 & 31;
        int qr2 = lane2 >> 2, qc2 = lane2 & 3;
        int k2 = ks2 * 16 + kk2 * 8 + qc2;
        int m = t2 * 128 + (mf2 >> 2) * 64 + (mf2 & 3) * 16 + qr2;
        v.x = rtf(wv[m * 256 + k2]);
        v.y = rtf(wv[(m + 8) * 256 + k2]);
        v.z = rtf(wv[m * 256 + k2 + 4]);
        v.w = rtf(wv[(m + 8) * 256 + k2 + 4]);
        *(float4*)&g_wtvF[idx2 * 4] = v;
    }
    if (idx < 256) {
        g_bcat[idx]       = bf[idx];
        g_bcat[256 + idx] = bg[idx];
        g_bcat[512 + idx] = bh[idx];
    }
}

// x -> B-fragment layout, tf32-rounded
__global__ void x_frag_kernel(const float* __restrict__ x) {
    int idx = blockIdx.x * 256 + threadIdx.x;
    int lane = idx & 31;
    int t1 = idx >> 5;
    int nf = t1 & 15; t1 >>= 4;
    int kk = t1 & 1;  t1 >>= 1;
    int ks = t1 & 15; t1 >>= 4;
    int nt = t1 & 31; t1 >>= 5;
    int n = nt * 128 + (nf >> 2) * 32 + (nf & 3) * 8 + (lane >> 2);
    int k = ks * 16 + kk * 8 + (lane & 3);
    const float* xb = x + (size_t)t1 * CHW;
    float2 v;
    v.x = rtf(xb[(size_t)k * HW + n]);
    v.y = rtf(xb[(size_t)(k + 4) * HW + n]);
    *(float2*)&g_xrF[(size_t)idx * 2] = v;
}

// ---------------------------------------------------------------------------
// HMMA tf32 conv GEMM (round-12 pipeline). BFRAG=true (conv1) writes bf16
// hi/lo planes via a smem-staged, fully-coalesced epilogue; BFRAG=false
// (conv2) writes f32 to d_out directly.
// ---------------------------------------------------------------------------
#define SSTRIDE 136
#define SA(s)       ((s) * 2048)
#define SBF(s)      (10240 + (s) * 2048)
#define SBR(s, kr)  (10240 + (s) * 2176 + (kr) * SSTRIDE)
#define CONV_SMEM   ((10240 + 5 * 2176) * 4)   // 84480 B
#define ESTR 66                                // epilogue staging stride (u32)

template <bool BFRAG>
__global__ __launch_bounds__(256, 2)
void conv_mma_kernel(const float* __restrict__ XB, const float* __restrict__ WTF,
                     const float* __restrict__ bias, float* __restrict__ Y) {
    extern __shared__ uint32_t dsm[];

    const int tid  = threadIdx.x;
    const int lane = tid & 31;
    const int warp = tid >> 5;
    const int mw   = warp >> 2;
    const int nw   = warp & 3;
    const int b    = blockIdx.z;
    const int nt   = blockIdx.x;
    const int n0   = nt * 128;
    const int mt   = blockIdx.y;
    const int m0   = mt * 128;

    const uint32_t sbase = (uint32_t)__cvta_generic_to_shared(dsm);
    const float* gA = WTF + (size_t)(mt * 16) * 2048;
    const float* gBF = XB + ((size_t)(b * 32 + nt) * 16) * 2048;
    const float* gBR = XB + (size_t)b * CHW + n0;

    float acc[4][4][4];
#pragma unroll
    for (int i = 0; i < 4; i++)
#pragma unroll
        for (int j = 0; j < 4; j++)
#pragma unroll
            for (int r = 0; r < 4; r++) acc[i][j][r] = 0.f;

    auto load_stage = [&](int s, int buf) {
#pragma unroll
        for (int h = 0; h < 2; h++) {
            int c = tid + h * 256;
            cpa16(sbase + (SA(buf) + c * 4) * 4, gA + (size_t)s * 2048 + c * 4);
            if (BFRAG) {
                cpa16(sbase + (SBF(buf) + c * 4) * 4, gBF + (size_t)s * 2048 + c * 4);
            } else {
                int kr = c >> 5, nc = (c & 31) * 4;
                cpa16(sbase + (SBR(buf, kr) + nc) * 4,
                      gBR + (size_t)(s * 16 + kr) * HW + nc);
            }
        }
    };

#pragma unroll
    for (int s = 0; s < 3; s++) { load_stage(s, s); CP_COMMIT(); }

    int buf = 0, nbuf = 3;
    for (int kt = 0; kt < 16; kt++) {
        if (kt < 13) load_stage(kt + 3, nbuf);
        CP_COMMIT();
        CP_WAIT3();
        __syncthreads();

#pragma unroll
        for (int kk = 0; kk < 2; kk++) {
            uint32_t af[4][4];
#pragma unroll
            for (int mi = 0; mi < 4; mi++) {
                const uint4 a4 = *(const uint4*)
                    &dsm[SA(buf) + ((kk * 8 + mw * 4 + mi) * 32 + lane) * 4];
                af[mi][0] = a4.x; af[mi][1] = a4.y; af[mi][2] = a4.z; af[mi][3] = a4.w;
            }
            uint32_t bfr[4][2];
            if (BFRAG) {
#pragma unroll
                for (int nj = 0; nj < 4; nj++) {
                    const uint2 b2 = *(const uint2*)
                        &dsm[SBF(buf) + ((kk * 16 + nw * 4 + nj) * 32 + lane) * 2];
                    bfr[nj][0] = b2.x; bfr[nj][1] = b2.y;
                }
            } else {
                const int qc = lane & 3, qr = lane >> 2;
                const uint32_t* B0 = dsm + SBR(buf, kk * 8 + qc) + nw * 32 + qr;
#pragma unroll
                for (int nj = 0; nj < 4; nj++) {
                    bfr[nj][0] = B0[nj * 8];
                    bfr[nj][1] = B0[4 * SSTRIDE + nj * 8];
                }
            }
#pragma unroll
            for (int mi = 0; mi < 4; mi++)
#pragma unroll
                for (int nj = 0; nj < 4; nj++)
                    mma_tf32(acc[mi][nj], af[mi], bfr[nj]);
        }
        if (++buf == 5)  buf = 0;
        if (++nbuf == 5) nbuf = 0;
    }

    if (BFRAG) {
        // conv1 epilogue: bias + bf16 hi/lo split, staged through smem so the
        // global stores are warp-coalesced uint2 (values bit-identical to the
        // former attn-side bfsplit of the f32 results).
        __syncthreads();   // main-loop smem reads complete; reuse dsm
        const int qr = lane >> 2, qc = lane & 3;
#pragma unroll
        for (int mi = 0; mi < 4; mi++) {
            int rlo = mw * 64 + mi * 16 + qr;       // local m-row 0..127
            int rhi = rlo + 8;
            float bv0 = bias[m0 + rlo];
            float bv1 = bias[m0 + rhi];
#pragma unroll
            for (int nj = 0; nj < 4; nj++) {
                int nc2 = nw * 16 + nj * 4 + qc;    // u32 col 0..63
                uint32_t h, l;
                bfsplit2(acc[mi][nj][0] + bv0, acc[mi][nj][1] + bv0, h, l);
                dsm[rlo * ESTR + nc2] = h;
                dsm[128 * ESTR + rlo * ESTR + nc2] = l;
                bfsplit2(acc[mi][nj][2] + bv1, acc[mi][nj][3] + bv1, h, l);
                dsm[rhi * ESTR + nc2] = h;
                dsm[128 * ESTR + rhi * ESTR + nc2] = l;
            }
        }
        __syncthreads();

        uint2* Y2 = (uint2*)Y;                      // g_ybf as uint2 (4 bf16 each)
        const size_t LOD2 = PS >> 2;                // +1 plane in uint2 units
#pragma unroll
        for (int j = 0; j < 16; j++) {
            int i = tid + j * 256;                  // uint2 slot 0..4095
            int row = i >> 5, colp = i & 31;
            int mrow = m0 + row;
            int pl = (mrow >> 8) * 2, c0 = mrow & 255;
            size_t base2 = ((((size_t)pl * 16 + b) * CHW + (size_t)c0 * HW + n0) >> 2)
                           + colp;
            uint2 h2 = *(const uint2*)&dsm[row * ESTR + colp * 2];
            uint2 l2 = *(const uint2*)&dsm[128 * ESTR + row * ESTR + colp * 2];
            Y2[base2]        = h2;
            Y2[base2 + LOD2] = l2;
        }
    } else {
        // conv2 epilogue: bias + f32 v2 stores to d_out
#pragma unroll
        for (int mi = 0; mi < 4; mi++) {
            int mr0 = m0 + mw * 64 + mi * 16 + (lane >> 2);
            float bv0 = bias[mr0];
            float bv1 = bias[mr0 + 8];
            float* y0 = Y + (size_t)b * CHW + (size_t)(mr0 & 255) * HW + n0;
            float* y1 = Y + (size_t)b * CHW + (size_t)((mr0 + 8) & 255) * HW + n0;
#pragma unroll
            for (int nj = 0; nj < 4; nj++) {
                int nc = nw * 32 + nj * 8 + 2 * (lane & 3);
                float2 v0 = make_float2(acc[mi][nj][0] + bv0, acc[mi][nj][1] + bv0);
                float2 v1 = make_float2(acc[mi][nj][2] + bv1, acc[mi][nj][3] + bv1);
                *(float2*)(y0 + nc) = v0;
                *(float2*)(y1 + nc) = v1;
            }
        }
    }
}

// ---------------------------------------------------------------------------
// Fused attention (round-15 version): pre-split bf16 planes -> pure cp.async
// loads into ldmatrix-ready smem; bf16x2 x3 GEMMs; split softmax.
// ---------------------------------------------------------------------------
#define WS   36
#define PL   2304
#define ATT_SMEM 37888

__global__ __launch_bounds__(256)
void attn_kernel(const __nv_bfloat16* __restrict__ yb, float* __restrict__ o) {
    extern __shared__ uint32_t sm[];
    const int bc = blockIdx.x;
    const __nv_bfloat16* Fh = yb + (size_t)bc * HW;
    const __nv_bfloat16* Fl = Fh + PS;
    const __nv_bfloat16* Gh = Fh + 2 * PS;
    const __nv_bfloat16* Gl = Fh + 3 * PS;
    const __nv_bfloat16* Hh = Fh + 4 * PS;
    const __nv_bfloat16* Hl = Fh + 5 * PS;

    float* red = (float*)(sm + 4 * PL);   // [64][4]

    const uint32_t sb = (uint32_t)__cvta_generic_to_shared(sm);
    const int tid  = threadIdx.x;
    const int lane = tid & 31;
    const int warp = tid >> 5;
    const int mt   = warp >> 1;
    const int nh   = warp & 1;
    const int qr   = lane >> 2;
    const int qc   = lane & 3;

    // phase 0: copy F,G hi/lo planes into [h][w-pair] smem (stride WS) via cp.async
#pragma unroll
    for (int it = 0; it < 2; it++) {
        int i = tid * 8 + it * 2048;
        int off = (i >> 6) * WS + ((i & 63) >> 1);
        cpa16(sb + (0 * PL + off) * 4, Fh + i);
        cpa16(sb + (1 * PL + off) * 4, Fl + i);
        cpa16(sb + (2 * PL + off) * 4, Gh + i);
        cpa16(sb + (3 * PL + off) * 4, Gl + i);
    }
    CP_COMMIT();
    CP_WAIT0();
    __syncthreads();

    // GEMM1 (bf16x2): S[w][v] = sum_h F[h][w] G[h][v]; operands via ldmatrix.trans
    float acc[4][4];
#pragma unroll
    for (int nj = 0; nj < 4; nj++)
#pragma unroll
        for (int r = 0; r < 4; r++) acc[nj][r] = 0.f;

    const int kselA = (lane & 7) + 8 * ((lane >> 4) & 1);
    const int mcolA = mt * 16 + 8 * ((lane >> 3) & 1);
    const int kselB = (lane & 7) + 8 * ((lane >> 3) & 1);
#pragma unroll
    for (int it = 0; it < 4; it++) {
        uint32_t aaddr = sb + ((it * 16 + kselA) * WS) * 4 + mcolA * 2;
        uint32_t aH[4], aL[4];
        LDSM4T(aH[0], aH[1], aH[2], aH[3], aaddr);
        LDSM4T(aL[0], aL[1], aL[2], aL[3], aaddr + PL * 4);
        uint32_t bbase = sb + 2 * PL * 4 + ((it * 16 + kselB) * WS) * 4 + (nh * 32) * 2;
#pragma unroll
        for (int nj = 0; nj < 4; nj++) {
            uint32_t bH[2], bL[2];
            LDSM2T(bH[0], bH[1], bbase + nj * 16);
            LDSM2T(bL[0], bL[1], bbase + nj * 16 + PL * 4);
            mma_bf16(acc[nj], aH, bH);
            mma_bf16(acc[nj], aH, bL);
            mma_bf16(acc[nj], aL, bH);
        }
    }

    // split softmax
    float mlo = -1e30f, mhi = -1e30f;
#pragma unroll
    for (int nj = 0; nj < 4; nj++) {
        mlo = fmaxf(mlo, fmaxf(acc[nj][0], acc[nj][1]));
        mhi = fmaxf(mhi, fmaxf(acc[nj][2], acc[nj][3]));
    }
    mlo = fmaxf(mlo, __shfl_xor_sync(0xffffffffu, mlo, 1));
    mlo = fmaxf(mlo, __shfl_xor_sync(0xffffffffu, mlo, 2));
    mhi = fmaxf(mhi, __shfl_xor_sync(0xffffffffu, mhi, 1));
    mhi = fmaxf(mhi, __shfl_xor_sync(0xffffffffu, mhi, 2));
    float slo = 0.f, shi = 0.f;
#pragma unroll
    for (int nj = 0; nj < 4; nj++) {
        acc[nj][0] = __expf(acc[nj][0] - mlo);
        acc[nj][1] = __expf(acc[nj][1] - mlo);
        acc[nj][2] = __expf(acc[nj][2] - mhi);
        acc[nj][3] = __expf(acc[nj][3] - mhi);
        slo += acc[nj][0] + acc[nj][1];
        shi += acc[nj][2] + acc[nj][3];
    }
    slo += __shfl_xor_sync(0xffffffffu, slo, 1);
    slo += __shfl_xor_sync(0xffffffffu, slo, 2);
    shi += __shfl_xor_sync(0xffffffffu, shi, 1);
    shi += __shfl_xor_sync(0xffffffffu, shi, 2);

    const int rlo = mt * 16 + qr, rhi = rlo + 8;
    if (qc == 0) {
        red[rlo * 4 + nh * 2]     = mlo;
        red[rlo * 4 + nh * 2 + 1] = slo;
        red[rhi * 4 + nh * 2]     = mhi;
        red[rhi * 4 + nh * 2 + 1] = shi;
    }
    __syncthreads();   // all GEMM1 plane reads complete; red published

    // phase 2 Hm copy issued NOW (overlaps combine + attn staging)
#pragma unroll
    for (int it = 0; it < 2; it++) {
        int i = tid * 8 + it * 2048;
        int off = (i >> 6) * WS + ((i & 63) >> 1);
        cpa16(sb + (0 * PL + off) * 4, Hh + i);
        cpa16(sb + (1 * PL + off) * 4, Hl + i);
    }
    CP_COMMIT();

    float scl_lo, scl_hi;
    {
        float4 r4 = *(const float4*)&red[rlo * 4];
        float M = fmaxf(r4.x, r4.z);
        float den = r4.y * __expf(r4.x - M) + r4.w * __expf(r4.z - M);
        scl_lo = __expf(mlo - M) / den;
        r4 = *(const float4*)&red[rhi * 4];
        M = fmaxf(r4.x, r4.z);
        den = r4.y * __expf(r4.x - M) + r4.w * __expf(r4.z - M);
        scl_hi = __expf(mhi - M) / den;
    }

    // attn -> [v][w] scalar bf16 hi/lo (overlays G planes)
    {
        uint32_t* sAtH = sm + 2 * PL;
        uint32_t* sAtL = sm + 3 * PL;
        __nv_bfloat16* pH = (__nv_bfloat16*)sAtH;
        __nv_bfloat16* pL = (__nv_bfloat16*)sAtL;
        const int wlo = mt * 16 + qr, whi = wlo + 8;
#pragma unroll
        for (int nj = 0; nj < 4; nj++) {
            const int v = nh * 32 + nj * 8 + 2 * qc;
#pragma unroll
            for (int r = 0; r < 4; r++) {
                float val = acc[nj][r] * ((r < 2) ? scl_lo : scl_hi);
                int vv = v + (r & 1);
                int ww = (r < 2) ? wlo : whi;
                __nv_bfloat16 h = __float2bfloat16_rn(val);
                pH[vv * (WS * 2) + ww] = h;
                pL[vv * (WS * 2) + ww] = __float2bfloat16_rn(val - __bfloat162float(h));
            }
        }
    }
    CP_WAIT0();
    __syncthreads();

    // GEMM2 (bf16x2): C[v][h] = sum_w attn[w][v] * Hm[h][w]  (= O^T), ldmatrix non-trans
#pragma unroll
    for (int nj = 0; nj < 4; nj++)
#pragma unroll
        for (int r = 0; r < 4; r++) acc[nj][r] = 0.f;

    const int mrowA2 = mt * 16 + (lane & 7) + 8 * ((lane >> 3) & 1);
    const int kcolA2 = 8 * ((lane >> 4) & 1);
    const int nrowB2 = nh * 32 + (lane & 7);
    const int kcolB2 = 8 * ((lane >> 3) & 1);
#pragma unroll
    for (int it = 0; it < 4; it++) {
        uint32_t aaddr = sb + 2 * PL * 4 + (mrowA2 * WS) * 4 + (it * 16 + kcolA2) * 2;
        uint32_t aH[4], aL[4];
        LDSM4N(aH[0], aH[1], aH[2], aH[3], aaddr);
        LDSM4N(aL[0], aL[1], aL[2], aL[3], aaddr + PL * 4);
#pragma unroll
        for (int nj = 0; nj < 4; nj++) {
            uint32_t baddr = sb + ((nrowB2 + nj * 8) * WS) * 4 + (it * 16 + kcolB2) * 2;
            uint32_t bH[2], bL[2];
            LDSM2N(bH[0], bH[1], baddr);
            LDSM2N(bL[0], bL[1], baddr + PL * 4);
            mma_bf16(acc[nj], aH, bH);
            mma_bf16(acc[nj], aH, bL);
            mma_bf16(acc[nj], aL, bH);
        }
    }

    // store O[h][v] (tf32-rounded for the final conv)
    float* O = o + (size_t)bc * HW;
    const int vr = mt * 16 + qr;
#pragma unroll
    for (int nj = 0; nj < 4; nj++) {
        const int hc = nh * 32 + nj * 8 + 2 * qc;
        O[hc * 64 + vr]           = rtf(acc[nj][0]);
        O[(hc + 1) * 64 + vr]     = rtf(acc[nj][1]);
        O[hc * 64 + vr + 8]       = rtf(acc[nj][2]);
        O[(hc + 1) * 64 + vr + 8] = rtf(acc[nj][3]);
    }
}

// ---------------------------------------------------------------------------
extern "C" void kernel_launch(void* const* d_in, const int* in_sizes, int n_in,
                              void* d_out, int out_size) {
    const float* x  = (const float*)d_in[0];
    const float* wf = (const float*)d_in[1];
    const float* bf = (const float*)d_in[2];
    const float* wg = (const float*)d_in[3];
    const float* bg = (const float*)d_in[4];
    const float* wh = (const float*)d_in[5];
    const float* bh = (const float*)d_in[6];
    const float* wv = (const float*)d_in[7];
    const float* bv = (const float*)d_in[8];

    float *ob, *xrF, *wtF, *wtvF, *bcat;
    __nv_bfloat16* ybf;
    cudaGetSymbolAddress((void**)&ybf,  g_ybf);
    cudaGetSymbolAddress((void**)&ob,   g_o);
    cudaGetSymbolAddress((void**)&xrF,  g_xrF);
    cudaGetSymbolAddress((void**)&wtF,  g_wtF);
    cudaGetSymbolAddress((void**)&wtvF, g_wtvF);
    cudaGetSymbolAddress((void**)&bcat, g_bcat);

    cudaFuncSetAttribute(conv_mma_kernel<true>,
                         cudaFuncAttributeMaxDynamicSharedMemorySize, CONV_SMEM);
    cudaFuncSetAttribute(conv_mma_kernel<false>,
                         cudaFuncAttributeMaxDynamicSharedMemorySize, CONV_SMEM);
    cudaFuncSetAttribute(attn_kernel,
                         cudaFuncAttributeMaxDynamicSharedMemorySize, ATT_SMEM);

    // 1) weights -> fragment layout; x -> fragment layout (tf32-rounded)
    prep_w_kernel<<<256, 256>>>(wf, wg, wh, wv, bf, bg, bh);
    x_frag_kernel<<<32768, 256>>>(x);

    // 2) fused f/g/h conv -> bf16 hi/lo planes (coalesced staged epilogue)
    conv_mma_kernel<true><<<dim3(32, 6, 16), 256, CONV_SMEM>>>(xrF, wtF, bcat, (float*)ybf);

    // 3) per-(b,c) attention
    attn_kernel<<<4096, 256, ATT_SMEM>>>(ybf, ob);

    // 4) output conv
    conv_mma_kernel<false><<<dim3(32, 2, 16), 256, CONV_SMEM>>>(ob, wtvF, bv, (float*)d_out);
}

// round 17
// speedup vs baseline: 1.1504x; 1.1077x over previous
#include <cuda_runtime.h>
#include <cuda_bf16.h>
#include <math.h>
#include <stdint.h>

#define BATCH 16
#define HW    4096
#define CHW   1048576u

// Scratch (no allocation allowed -> __device__ globals)
__device__ float g_y[3ull * 16777216ull];   // fx, gx, hx (f32)
__device__ float g_o[16777216ull];          // attention output (tf32-rounded)
__device__ float g_wtF[768 * 256];          // concat(wf,wg,wh), A-fragment layout
__device__ float g_wtvF[256 * 256];         // wv, A-fragment layout
__device__ float g_bcat[768];

__device__ __forceinline__ uint32_t f2tf32(float v) {
    uint32_t r;
    asm("cvt.rna.tf32.f32 %0, %1;" : "=r"(r) : "f"(v));
    return r;
}
__device__ __forceinline__ float rtf(float v) { return __uint_as_float(f2tf32(v)); }

__device__ __forceinline__ void mma_tf32(float* c, const uint32_t* a, const uint32_t* b) {
    asm volatile(
        "mma.sync.aligned.m16n8k8.row.col.f32.tf32.tf32.f32 "
        "{%0,%1,%2,%3}, {%4,%5,%6,%7}, {%8,%9}, {%0,%1,%2,%3};"
        : "+f"(c[0]), "+f"(c[1]), "+f"(c[2]), "+f"(c[3])
        : "r"(a[0]), "r"(a[1]), "r"(a[2]), "r"(a[3]), "r"(b[0]), "r"(b[1]));
}

__device__ __forceinline__ void mma_bf16(float* c, const uint32_t* a, const uint32_t* b) {
    asm volatile(
        "mma.sync.aligned.m16n8k16.row.col.f32.bf16.bf16.f32 "
        "{%0,%1,%2,%3}, {%4,%5,%6,%7}, {%8,%9}, {%0,%1,%2,%3};"
        : "+f"(c[0]), "+f"(c[1]), "+f"(c[2]), "+f"(c[3])
        : "r"(a[0]), "r"(a[1]), "r"(a[2]), "r"(a[3]), "r"(b[0]), "r"(b[1]));
}

// pack two f32 into bf16x2: low half = first arg, high = second
__device__ __forceinline__ uint32_t bfpack(float lo_elem, float hi_elem) {
    uint32_t r;
    asm("cvt.rn.bf16x2.f32 %0, %2, %1;" : "=r"(r) : "f"(lo_elem), "f"(hi_elem));
    return r;
}
__device__ __forceinline__ void bfsplit2(float x0, float x1, uint32_t& hi, uint32_t& lo) {
    hi = bfpack(x0, x1);
    float h0 = __uint_as_float(hi << 16);
    float h1 = __uint_as_float(hi & 0xffff0000u);
    lo = bfpack(x0 - h0, x1 - h1);
}

__device__ __forceinline__ void cpa16(uint32_t s, const void* g) {
    asm volatile("cp.async.cg.shared.global [%0], [%1], 16;" :: "r"(s), "l"(g));
}
#define CP_COMMIT()  asm volatile("cp.async.commit_group;" ::: "memory")
#define CP_WAIT3()   asm volatile("cp.async.wait_group 3;" ::: "memory")

#define LDSM4T(r0,r1,r2,r3,a) \
    asm volatile("ldmatrix.sync.aligned.m8n8.x4.trans.shared.b16 {%0,%1,%2,%3}, [%4];" \
                 : "=r"(r0),"=r"(r1),"=r"(r2),"=r"(r3) : "r"(a))
#define LDSM2T(r0,r1,a) \
    asm volatile("ldmatrix.sync.aligned.m8n8.x2.trans.shared.b16 {%0,%1}, [%2];" \
                 : "=r"(r0),"=r"(r1) : "r"(a))
#define LDSM4N(r0,r1,r2,r3,a) \
    asm volatile("ldmatrix.sync.aligned.m8n8.x4.shared.b16 {%0,%1,%2,%3}, [%4];" \
                 : "=r"(r0),"=r"(r1),"=r"(r2),"=r"(r3) : "r"(a))
#define LDSM2N(r0,r1,a) \
    asm volatile("ldmatrix.sync.aligned.m8n8.x2.shared.b16 {%0,%1}, [%2];" \
                 : "=r"(r0),"=r"(r1) : "r"(a))

// ---------------------------------------------------------------------------
// Prep: weights -> A-fragment layout, tf32-rounded; concat biases.
// ---------------------------------------------------------------------------
__global__ void prep_w_kernel(const float* __restrict__ wf, const float* __restrict__ wg,
                              const float* __restrict__ wh, const float* __restrict__ wv,
                              const float* __restrict__ bf, const float* __restrict__ bg,
                              const float* __restrict__ bh) {
    int idx = blockIdx.x * 256 + threadIdx.x;
    int lane = idx & 31;
    int t1 = idx >> 5;
    int mf = t1 & 7;  t1 >>= 3;
    int kk = t1 & 1;  t1 >>= 1;
    int ks = t1 & 15; t1 >>= 4;
    int qr = lane >> 2, qc = lane & 3;
    int k = ks * 16 + kk * 8 + qc;
    float4 v;
    if (idx < 49152) {
        int m = t1 * 128 + (mf >> 2) * 64 + (mf & 3) * 16 + qr;
        const float* w = (m < 256) ? wf : (m < 512) ? wg : wh;
        int mm = m & 255;
        v.x = rtf(w[mm * 256 + k]);
        v.y = rtf(w[(mm + 8) * 256 + k]);
        v.z = rtf(w[mm * 256 + k + 4]);
        v.w = rtf(w[(mm + 8) * 256 + k + 4]);
        *(float4*)&g_wtF[idx * 4] = v;
    } else {
        int idx2 = idx - 49152;
        int t2 = idx2 >> 5;
        int mf2 = t2 & 7;  t2 >>= 3;
        int kk2 = t2 & 1;  t2 >>= 1;
        int ks2 = t2 & 15; t2 >>= 4;
        int lane2 = idx2 & 31;
        int qr2 = lane2 >> 2, qc2 = lane2 & 3;
        int k2 = ks2 * 16 + kk2 * 8 + qc2;
        int m = t2 * 128 + (mf2 >> 2) * 64 + (mf2 & 3) * 16 + qr2;
        v.x = rtf(wv[m * 256 + k2]);
        v.y = rtf(wv[(m + 8) * 256 + k2]);
        v.z = rtf(wv[m * 256 + k2 + 4]);
        v.w = rtf(wv[(m + 8) * 256 + k2 + 4]);
        *(float4*)&g_wtvF[idx2 * 4] = v;
    }
    if (idx < 256) {
        g_bcat[idx]       = bf[idx];
        g_bcat[256 + idx] = bg[idx];
        g_bcat[512 + idx] = bh[idx];
    }
}

// ---------------------------------------------------------------------------
// HMMA tf32 conv GEMM (round-12/14 pipeline). B always row layout via SBR
// cp.async (bank-exact fragment LDS). RNDB=true applies cvt.rna.tf32 to the
// B fragments after the LDS — bit-identical to reading pre-rounded data, so
// the separate x-rounding pass is eliminated.
// ---------------------------------------------------------------------------
#define SSTRIDE 136
#define SA(s)       ((s) * 2048)
#define SBR(s, kr)  (10240 + (s) * 2176 + (kr) * SSTRIDE)
#define CONV_SMEM   ((10240 + 5 * 2176) * 4)   // 84480 B

template <bool RNDB>
__global__ __launch_bounds__(256, 2)
void conv_mma_kernel(const float* __restrict__ XB, const float* __restrict__ WTF,
                     const float* __restrict__ bias, float* __restrict__ Y) {
    extern __shared__ uint32_t dsm[];

    const int tid  = threadIdx.x;
    const int lane = tid & 31;
    const int warp = tid >> 5;
    const int mw   = warp >> 2;
    const int nw   = warp & 3;
    const int b    = blockIdx.z;
    const int nt   = blockIdx.x;
    const int n0   = nt * 128;
    const int mt   = blockIdx.y;
    const int m0   = mt * 128;

    const uint32_t sbase = (uint32_t)__cvta_generic_to_shared(dsm);
    const float* gA  = WTF + (size_t)(mt * 16) * 2048;
    const float* gBR = XB + (size_t)b * CHW + n0;

    float acc[4][4][4];
#pragma unroll
    for (int i = 0; i < 4; i++)
#pragma unroll
        for (int j = 0; j < 4; j++)
#pragma unroll
            for (int r = 0; r < 4; r++) acc[i][j][r] = 0.f;

    auto load_stage = [&](int s, int buf) {
#pragma unroll
        for (int h = 0; h < 2; h++) {
            int c = tid + h * 256;
            cpa16(sbase + (SA(buf) + c * 4) * 4, gA + (size_t)s * 2048 + c * 4);
            int kr = c >> 5, nc = (c & 31) * 4;
            cpa16(sbase + (SBR(buf, kr) + nc) * 4,
                  gBR + (size_t)(s * 16 + kr) * HW + nc);
        }
    };

    // prologue: stages 0..2 into buffers 0..2
#pragma unroll
    for (int s = 0; s < 3; s++) { load_stage(s, s); CP_COMMIT(); }

    int buf = 0, nbuf = 3;
    for (int kt = 0; kt < 16; kt++) {
        if (kt < 13) load_stage(kt + 3, nbuf);
        CP_COMMIT();
        CP_WAIT3();          // own stage-kt copies retired
        __syncthreads();     // publish stage kt; fences WAR for next issue

#pragma unroll
        for (int kk = 0; kk < 2; kk++) {
            uint32_t af[4][4];
#pragma unroll
            for (int mi = 0; mi < 4; mi++) {
                const uint4 a4 = *(const uint4*)
                    &dsm[SA(buf) + ((kk * 8 + mw * 4 + mi) * 32 + lane) * 4];
                af[mi][0] = a4.x; af[mi][1] = a4.y; af[mi][2] = a4.z; af[mi][3] = a4.w;
            }
            uint32_t bfr[4][2];
            {
                const int qc = lane & 3, qr = lane >> 2;
                const uint32_t* B0 = dsm + SBR(buf, kk * 8 + qc) + nw * 32 + qr;
#pragma unroll
                for (int nj = 0; nj < 4; nj++) {
                    uint32_t b0 = B0[nj * 8];
                    uint32_t b1 = B0[4 * SSTRIDE + nj * 8];
                    if (RNDB) {
                        b0 = f2tf32(__uint_as_float(b0));
                        b1 = f2tf32(__uint_as_float(b1));
                    }
                    bfr[nj][0] = b0;
                    bfr[nj][1] = b1;
                }
            }
#pragma unroll
            for (int mi = 0; mi < 4; mi++)
#pragma unroll
                for (int nj = 0; nj < 4; nj++)
                    mma_tf32(acc[mi][nj], af[mi], bfr[nj]);
        }
        if (++buf == 5)  buf = 0;
        if (++nbuf == 5) nbuf = 0;
    }

    // epilogue: bias + f32 v2 stores (handles the concat plane scatter)
#pragma unroll
    for (int mi = 0; mi < 4; mi++) {
        int mr0 = m0 + mw * 64 + mi * 16 + (lane >> 2);
        float bv0 = bias[mr0];
        float bv1 = bias[mr0 + 8];
        float* y0 = Y + ((size_t)(mr0 >> 8) * BATCH + b) * CHW + (size_t)(mr0 & 255) * HW + n0;
        int mr1 = mr0 + 8;
        float* y1 = Y + ((size_t)(mr1 >> 8) * BATCH + b) * CHW + (size_t)(mr1 & 255) * HW + n0;
#pragma unroll
        for (int nj = 0; nj < 4; nj++) {
            int nc = nw * 32 + nj * 8 + 2 * (lane & 3);
            float2 v0 = make_float2(acc[mi][nj][0] + bv0, acc[mi][nj][1] + bv0);
            float2 v1 = make_float2(acc[mi][nj][2] + bv1, acc[mi][nj][3] + bv1);
            *(float2*)(y0 + nc) = v0;
            *(float2*)(y1 + nc) = v1;
        }
    }
}

// ---------------------------------------------------------------------------
// Fused attention — round-13/14 measured-best version (f32 input, in-kernel
// bf16x2 hi/lo split, ldmatrix operand paths, split softmax).
// ---------------------------------------------------------------------------
#define WS   36
#define PL   2304
#define ATT_SMEM 37888

__global__ __launch_bounds__(256)
void attn_kernel(const float* __restrict__ y, float* __restrict__ o) {
    extern __shared__ uint32_t sm[];
    const int bc = blockIdx.x;
    const size_t BCHW = (size_t)BATCH * CHW;
    const float* F  = y + (size_t)bc * HW;
    const float* G  = y + BCHW + (size_t)bc * HW;
    const float* Hm = y + 2 * BCHW + (size_t)bc * HW;

    uint32_t* sFh = sm;
    uint32_t* sFl = sm + PL;
    uint32_t* sGh = sm + 2 * PL;
    uint32_t* sGl = sm + 3 * PL;
    float*    red = (float*)(sm + 4 * PL);   // [64][4]

    const uint32_t sb = (uint32_t)__cvta_generic_to_shared(sm);
    const int tid  = threadIdx.x;
    const int lane = tid & 31;
    const int warp = tid >> 5;
    const int mt   = warp >> 1;
    const int nh   = warp & 1;
    const int qr   = lane >> 2;
    const int qc   = lane & 3;

    // phase 0: F,G natural [h][w], bf16 hi/lo planes, fully vectorized
#pragma unroll
    for (int it = 0; it < 4; it++) {
        int i = tid * 4 + it * 1024;
        int off = (i >> 6) * WS + ((i & 63) >> 1);
        float4 f = *(const float4*)&F[i];
        float4 g = *(const float4*)&G[i];
        uint32_t hA, lA, hB, lB;
        bfsplit2(f.x, f.y, hA, lA); bfsplit2(f.z, f.w, hB, lB);
        *(uint2*)&sFh[off] = make_uint2(hA, hB);
        *(uint2*)&sFl[off] = make_uint2(lA, lB);
        bfsplit2(g.x, g.y, hA, lA); bfsplit2(g.z, g.w, hB, lB);
        *(uint2*)&sGh[off] = make_uint2(hA, hB);
        *(uint2*)&sGl[off] = make_uint2(lA, lB);
    }
    __syncthreads();

    // GEMM1 (bf16x2): S[w][v] = sum_h F[h][w] G[h][v]; operands via ldmatrix.trans
    float acc[4][4];
#pragma unroll
    for (int nj = 0; nj < 4; nj++)
#pragma unroll
        for (int r = 0; r < 4; r++) acc[nj][r] = 0.f;

    const int kselA = (lane & 7) + 8 * ((lane >> 4) & 1);
    const int mcolA = mt * 16 + 8 * ((lane >> 3) & 1);
    const int kselB = (lane & 7) + 8 * ((lane >> 3) & 1);
#pragma unroll
    for (int it = 0; it < 4; it++) {
        uint32_t aaddr = sb + ((it * 16 + kselA) * WS) * 4 + mcolA * 2;
        uint32_t aH[4], aL[4];
        LDSM4T(aH[0], aH[1], aH[2], aH[3], aaddr);
        LDSM4T(aL[0], aL[1], aL[2], aL[3], aaddr + PL * 4);
        uint32_t bbase = sb + 2 * PL * 4 + ((it * 16 + kselB) * WS) * 4 + (nh * 32) * 2;
#pragma unroll
        for (int nj = 0; nj < 4; nj++) {
            uint32_t bH[2], bL[2];
            LDSM2T(bH[0], bH[1], bbase + nj * 16);
            LDSM2T(bL[0], bL[1], bbase + nj * 16 + PL * 4);
            mma_bf16(acc[nj], aH, bH);
            mma_bf16(acc[nj], aH, bL);
            mma_bf16(acc[nj], aL, bH);
        }
    }

    // split softmax
    float mlo = -1e30f, mhi = -1e30f;
#pragma unroll
    for (int nj = 0; nj < 4; nj++) {
        mlo = fmaxf(mlo, fmaxf(acc[nj][0], acc[nj][1]));
        mhi = fmaxf(mhi, fmaxf(acc[nj][2], acc[nj][3]));
    }
    mlo = fmaxf(mlo, __shfl_xor_sync(0xffffffffu, mlo, 1));
    mlo = fmaxf(mlo, __shfl_xor_sync(0xffffffffu, mlo, 2));
    mhi = fmaxf(mhi, __shfl_xor_sync(0xffffffffu, mhi, 1));
    mhi = fmaxf(mhi, __shfl_xor_sync(0xffffffffu, mhi, 2));
    float slo = 0.f, shi = 0.f;
#pragma unroll
    for (int nj = 0; nj < 4; nj++) {
        acc[nj][0] = __expf(acc[nj][0] - mlo);
        acc[nj][1] = __expf(acc[nj][1] - mlo);
        acc[nj][2] = __expf(acc[nj][2] - mhi);
        acc[nj][3] = __expf(acc[nj][3] - mhi);
        slo += acc[nj][0] + acc[nj][1];
        shi += acc[nj][2] + acc[nj][3];
    }
    slo += __shfl_xor_sync(0xffffffffu, slo, 1);
    slo += __shfl_xor_sync(0xffffffffu, slo, 2);
    shi += __shfl_xor_sync(0xffffffffu, shi, 1);
    shi += __shfl_xor_sync(0xffffffffu, shi, 2);

    const int rlo = mt * 16 + qr, rhi = rlo + 8;
    if (qc == 0) {
        red[rlo * 4 + nh * 2]     = mlo;
        red[rlo * 4 + nh * 2 + 1] = slo;
        red[rhi * 4 + nh * 2]     = mhi;
        red[rhi * 4 + nh * 2 + 1] = shi;
    }
    __syncthreads();   // all GEMM1 plane reads complete; red published

    float scl_lo, scl_hi;
    {
        float4 r4 = *(const float4*)&red[rlo * 4];
        float M = fmaxf(r4.x, r4.z);
        float den = r4.y * __expf(r4.x - M) + r4.w * __expf(r4.z - M);
        scl_lo = __expf(mlo - M) / den;
        r4 = *(const float4*)&red[rhi * 4];
        M = fmaxf(r4.x, r4.z);
        den = r4.y * __expf(r4.x - M) + r4.w * __expf(r4.z - M);
        scl_hi = __expf(mhi - M) / den;
    }

    // phase 2 staging (overlays phase-1 planes; red untouched)
    uint32_t* sHmH = sm;
    uint32_t* sHmL = sm + PL;
    uint32_t* sAtH = sm + 2 * PL;
    uint32_t* sAtL = sm + 3 * PL;

    // attn -> [v][w] scalar bf16 hi/lo
    {
        __nv_bfloat16* pH = (__nv_bfloat16*)sAtH;
        __nv_bfloat16* pL = (__nv_bfloat16*)sAtL;
        const int wlo = mt * 16 + qr, whi = wlo + 8;
#pragma unroll
        for (int nj = 0; nj < 4; nj++) {
            const int v = nh * 32 + nj * 8 + 2 * qc;
#pragma unroll
            for (int r = 0; r < 4; r++) {
                float val = acc[nj][r] * ((r < 2) ? scl_lo : scl_hi);
                int vv = v + (r & 1);
                int ww = (r < 2) ? wlo : whi;
                __nv_bfloat16 h = __float2bfloat16_rn(val);
                pH[vv * (WS * 2) + ww] = h;
                pL[vv * (WS * 2) + ww] = __float2bfloat16_rn(val - __bfloat162float(h));
            }
        }
    }
    // Hm -> natural [h][w] hi/lo planes, vectorized
#pragma unroll
    for (int it = 0; it < 4; it++) {
        int i = tid * 4 + it * 1024;
        int off = (i >> 6) * WS + ((i & 63) >> 1);
        float4 v = *(const float4*)&Hm[i];
        uint32_t hA, lA, hB, lB;
        bfsplit2(v.x, v.y, hA, lA); bfsplit2(v.z, v.w, hB, lB);
        *(uint2*)&sHmH[off] = make_uint2(hA, hB);
        *(uint2*)&sHmL[off] = make_uint2(lA, lB);
    }
    __syncthreads();

    // GEMM2 (bf16x2): C[v][h] = sum_w attn[w][v] * Hm[h][w]  (= O^T), ldmatrix non-trans
#pragma unroll
    for (int nj = 0; nj < 4; nj++)
#pragma unroll
        for (int r = 0; r < 4; r++) acc[nj][r] = 0.f;

    const int mrowA2 = mt * 16 + (lane & 7) + 8 * ((lane >> 3) & 1);
    const int kcolA2 = 8 * ((lane >> 4) & 1);
    const int nrowB2 = nh * 32 + (lane & 7);
    const int kcolB2 = 8 * ((lane >> 3) & 1);
#pragma unroll
    for (int it = 0; it < 4; it++) {
        uint32_t aaddr = sb + 2 * PL * 4 + (mrowA2 * WS) * 4 + (it * 16 + kcolA2) * 2;
        uint32_t aH[4], aL[4];
        LDSM4N(aH[0], aH[1], aH[2], aH[3], aaddr);
        LDSM4N(aL[0], aL[1], aL[2], aL[3], aaddr + PL * 4);
#pragma unroll
        for (int nj = 0; nj < 4; nj++) {
            uint32_t baddr = sb + ((nrowB2 + nj * 8) * WS) * 4 + (it * 16 + kcolB2) * 2;
            uint32_t bH[2], bL[2];
            LDSM2N(bH[0], bH[1], baddr);
            LDSM2N(bL[0], bL[1], baddr + PL * 4);
            mma_bf16(acc[nj], aH, bH);
            mma_bf16(acc[nj], aH, bL);
            mma_bf16(acc[nj], aL, bH);
        }
    }

    // store O[h][v] (tf32-rounded for the final conv)
    float* O = o + (size_t)bc * HW;
    const int vr = mt * 16 + qr;
#pragma unroll
    for (int nj = 0; nj < 4; nj++) {
        const int hc = nh * 32 + nj * 8 + 2 * qc;
        O[hc * 64 + vr]           = rtf(acc[nj][0]);
        O[(hc + 1) * 64 + vr]     = rtf(acc[nj][1]);
        O[hc * 64 + vr + 8]       = rtf(acc[nj][2]);
        O[(hc + 1) * 64 + vr + 8] = rtf(acc[nj][3]);
    }
}

// ---------------------------------------------------------------------------
extern "C" void kernel_launch(void* const* d_in, const int* in_sizes, int n_in,
                              void* d_out, int out_size) {
    const float* x  = (const float*)d_in[0];
    const float* wf = (const float*)d_in[1];
    const float* bf = (const float*)d_in[2];
    const float* wg = (const float*)d_in[3];
    const float* bg = (const float*)d_in[4];
    const float* wh = (const float*)d_in[5];
    const float* bh = (const float*)d_in[6];
    const float* wv = (const float*)d_in[7];
    const float* bv = (const float*)d_in[8];

    float *yb, *ob, *wtF, *wtvF, *bcat;
    cudaGetSymbolAddress((void**)&yb,   g_y);
    cudaGetSymbolAddress((void**)&ob,   g_o);
    cudaGetSymbolAddress((void**)&wtF,  g_wtF);
    cudaGetSymbolAddress((void**)&wtvF, g_wtvF);
    cudaGetSymbolAddress((void**)&bcat, g_bcat);

    cudaFuncSetAttribute(conv_mma_kernel<true>,
                         cudaFuncAttributeMaxDynamicSharedMemorySize, CONV_SMEM);
    cudaFuncSetAttribute(conv_mma_kernel<false>,
                         cudaFuncAttributeMaxDynamicSharedMemorySize, CONV_SMEM);
    cudaFuncSetAttribute(attn_kernel,
                         cudaFuncAttributeMaxDynamicSharedMemorySize, ATT_SMEM);

    // 1) weights -> fragment layout (tf32-rounded); biases concat
    prep_w_kernel<<<256, 256>>>(wf, wg, wh, wv, bf, bg, bh);

    // 2) fused f/g/h conv: reads raw x (B rounded in-fragment), writes f32 g_y
    conv_mma_kernel<true><<<dim3(32, 6, 16), 256, CONV_SMEM>>>(x, wtF, bcat, yb);

    // 3) per-(b,c) attention
    attn_kernel<<<4096, 256, ATT_SMEM>>>(yb, ob);

    // 4) output conv: reads pre-rounded g_o, no B rounding needed
    conv_mma_kernel<false><<<dim3(32, 2, 16), 256, CONV_SMEM>>>(ob, wtvF, bv, (float*)d_out);
}